// round 10
// baseline (speedup 1.0000x reference)
#include <cuda_runtime.h>

typedef unsigned long long u64;

// Binary expansion of 1/(2*pi), preceded by 160 zero bits of padding so the
// window index p0 = e + 10 is always >= 0 for fp32 exponents of a = x*pi.
__constant__ unsigned c_PH[14] = {
    0u, 0u, 0u, 0u, 0u,
    0x28BE60DBu, 0x9391054Au, 0x7F09D5F4u, 0x7D4D3770u,
    0x36D8A566u, 0x4F10E410u, 0x7F9458EAu, 0xF7AEF158u, 0x6DC91B8Eu
};

// ---- packed f32x2 helpers (sm_103a FFMA2 path) -----------------------------
__device__ __forceinline__ void fma2(u64 &acc, u64 w, u64 xx) {
    asm("fma.rn.f32x2 %0, %1, %2, %0;" : "+l"(acc) : "l"(w), "l"(xx));
}
__device__ __forceinline__ u64 dup2(float s) {
    u64 r; asm("mov.b64 %0, {%1, %1};" : "=l"(r) : "f"(s)); return r;
}
__device__ __forceinline__ void unpack2(u64 v, float &lo, float &hi) {
    asm("mov.b64 {%0, %1}, %2;" : "=f"(lo), "=f"(hi) : "l"(v));
}
// acc[0..31] (64 packed fp32 outputs) += x * W[row][0..63]; row in shared.
__device__ __forceinline__ void row_fma(u64 *acc, const float *wrow, u64 xx) {
    const ulonglong2 *p = reinterpret_cast<const ulonglong2 *>(wrow);
#pragma unroll
    for (int q = 0; q < 16; ++q) {
        ulonglong2 w = p[q];
        fma2(acc[2 * q + 0], w.x, xx);
        fma2(acc[2 * q + 1], w.y, xx);
    }
}

// Shared layout (floats): [0,19456) W0 | [19456,23552) W1 | [23552,27648) W2 | [27648,27904) W3
#define SW1_OFF 19456
#define SW2_OFF 23552
#define SW3_OFF 27648
#define SMEM_FLOATS 27904
#define SMEM_BYTES (SMEM_FLOATS * 4 + 64)

__global__ void __launch_bounds__(256, 1)
tri_mlp_kernel(const float *__restrict__ pos, const float *__restrict__ aabb,
               const float *__restrict__ tri, const float *__restrict__ gW0,
               const float *__restrict__ gW1, const float *__restrict__ gW2,
               const float *__restrict__ gW3, float *__restrict__ out, int N)
{
    extern __shared__ float sW[];
    unsigned *sPH = (unsigned *)(sW + SMEM_FLOATS);
    const int tid = threadIdx.x;

    // Cooperative weight staging into shared
    {
        float4 *d0 = (float4 *)sW;                 const float4 *s0 = (const float4 *)gW0;
        for (int i = tid; i < 4864; i += 256) d0[i] = s0[i];
        float4 *d1 = (float4 *)(sW + SW1_OFF);     const float4 *s1 = (const float4 *)gW1;
        for (int i = tid; i < 1024; i += 256) d1[i] = s1[i];
        float4 *d2 = (float4 *)(sW + SW2_OFF);     const float4 *s2 = (const float4 *)gW2;
        for (int i = tid; i < 1024; i += 256) d2[i] = s2[i];
        float4 *d3 = (float4 *)(sW + SW3_OFF);     const float4 *s3 = (const float4 *)gW3;
        for (int i = tid; i < 64; i += 256) d3[i] = s3[i];
        if (tid < 14) sPH[tid] = c_PH[tid];
    }
    __syncthreads();

    const int idx = blockIdx.x * 256 + tid;
    if (idx >= N) return;

    const float px = pos[idx * 3 + 0];
    const float py = pos[idx * 3 + 1];
    const float pz = pos[idx * 3 + 2];
    const float mn0 = aabb[0], mn1 = aabb[1], mn2 = aabb[2];
    const float mx0 = aabb[3], mx1 = aabb[4], mx2 = aabb[5];
    // IEEE-exact normalization (no contraction), to match the reference's xn bitwise
    const float xn0 = __fdiv_rn(__fsub_rn(px, mn0), __fsub_rn(mx0, mn0));
    const float xn1 = __fdiv_rn(__fsub_rn(py, mn1), __fsub_rn(mx1, mn1));
    const float xn2 = __fdiv_rn(__fsub_rn(pz, mn2), __fsub_rn(mx2, mn2));
    const bool sel = (xn0 > 0.f) && (xn0 < 1.f) && (xn1 > 0.f) && (xn1 < 1.f) &&
                     (xn2 > 0.f) && (xn2 < 1.f);
    const float sc0 = 2.f * xn0 - 1.f;
    const float sc1 = 2.f * xn1 - 1.f;
    const float sc2 = 2.f * xn2 - 1.f;

    // ---------------- Layer 0 accumulation (streamed features) --------------
    u64 acc[32];
#pragma unroll
    for (int q = 0; q < 32; ++q) acc[q] = 0ull;

    const float xnv[3] = {xn0, xn1, xn2};

    // Frequency features: sin/cos(2^k * a), a = fl(x * pi_f32). One 128-bit
    // window of 1/(2pi)'s bits serves all k (shift 1 bit per k).
#pragma unroll
    for (int d = 0; d < 3; ++d) {
        const float a = __fmul_rn(xnv[d], 3.14159274101257324f); // pi_f32
        unsigned ab = __float_as_uint(a);
        const float sgn = (ab & 0x80000000u) ? -1.f : 1.f;
        ab &= 0x7FFFFFFFu;
        int e = (int)(ab >> 23);
        unsigned m = ab & 0x007FFFFFu;
        if (e) m |= 0x00800000u; else e = 1;  // denormal: a = m * 2^(1-150)
        const int p0 = e + 10;                // window start bit in padded stream
        int wq = p0 >> 5;
        const int rr = p0 & 31;
        wq = min(wq, 8);
        const u64 A = ((u64)sPH[wq] << 32) | sPH[wq + 1];
        const u64 B = ((u64)sPH[wq + 2] << 32) | sPH[wq + 3];
        const u64 C = ((u64)sPH[wq + 4] << 32) | sPH[wq + 5];
        u64 Ghi, Glo;
        if (rr) {
            Ghi = (A << rr) | (B >> (64 - rr));
            Glo = (B << rr) | (C >> (64 - rr));
        } else {
            Ghi = A; Glo = B;
        }
        const u64 m64 = (u64)m;
        const float *wrow = sW + d * 96 * 64;
#pragma unroll 2
        for (int k = 0; k < 48; ++k) {
            const u64 fr = m64 * Ghi;                  // frac(m*G) in Q0.64
            const int r32 = (int)(unsigned)(fr >> 32); // centered top 32 bits
            const float u = (float)r32 * 4.656612873077392578e-10f; // 2^-31
            const float s = sinpif(u) * sgn;  // sin(2pi*frac) = sin(2^k a)
            const float c = cospif(u);
            row_fma(acc, wrow, dup2(s)); wrow += 64;
            row_fma(acc, wrow, dup2(c)); wrow += 64;
            Ghi = (Ghi << 1) | (Glo >> 63);   // k -> k+1: shift window 1 bit
            Glo <<= 1;
        }
    }

    // Triplane bilinear features (L2-resident table)
    float f[16];
#pragma unroll
    for (int j = 0; j < 16; ++j) f[j] = 0.f;
    const float scv[3] = {sc0, sc1, sc2};
#pragma unroll
    for (int p = 0; p < 3; ++p) {
        const float cx = (p == 2) ? scv[1] : scv[0];
        const float cy = (p == 0) ? scv[1] : scv[2];
        const float gx = (cx + 1.f) * 0.5f * 31.f;
        const float gy = (cy + 1.f) * 0.5f * 31.f;
        const float x0f = fminf(fmaxf(floorf(gx), 0.f), 31.f);
        const float y0f = fminf(fmaxf(floorf(gy), 0.f), 31.f);
        const int x0 = (int)x0f, y0 = (int)y0f;
        const int x1 = min(x0 + 1, 31), y1 = min(y0 + 1, 31);
        const float wx = gx - x0f, wy = gy - y0f;
        const float w00 = (1.f - wx) * (1.f - wy);
        const float w01 = wx * (1.f - wy);
        const float w10 = (1.f - wx) * wy;
        const float w11 = wx * wy;
        const float *bp = tri + p * 16384;
        const float4 *c00 = (const float4 *)(bp + (y0 * 32 + x0) * 16);
        const float4 *c01 = (const float4 *)(bp + (y0 * 32 + x1) * 16);
        const float4 *c10 = (const float4 *)(bp + (y1 * 32 + x0) * 16);
        const float4 *c11 = (const float4 *)(bp + (y1 * 32 + x1) * 16);
#pragma unroll
        for (int j = 0; j < 4; ++j) {
            const float4 v00 = c00[j], v01 = c01[j], v10 = c10[j], v11 = c11[j];
            f[4 * j + 0] += v00.x * w00 + v01.x * w01 + v10.x * w10 + v11.x * w11;
            f[4 * j + 1] += v00.y * w00 + v01.y * w01 + v10.y * w10 + v11.y * w11;
            f[4 * j + 2] += v00.z * w00 + v01.z * w01 + v10.z * w10 + v11.z * w11;
            f[4 * j + 3] += v00.w * w00 + v01.w * w01 + v10.w * w10 + v11.w * w11;
        }
    }
#pragma unroll
    for (int t = 0; t < 16; ++t)
        row_fma(acc, sW + (288 + t) * 64, dup2(f[t]));

    // sin activation (preacts O(1): intrinsic path is accurate here)
    float h[64];
#pragma unroll
    for (int q = 0; q < 32; ++q) {
        float lo, hi; unpack2(acc[q], lo, hi);
        h[2 * q + 0] = __sinf(lo);
        h[2 * q + 1] = __sinf(hi);
    }

    // ---------------- Layer 1 ----------------
    {
        u64 a2[32];
#pragma unroll
        for (int q = 0; q < 32; ++q) a2[q] = 0ull;
        const float *W1s = sW + SW1_OFF;
#pragma unroll
        for (int i = 0; i < 64; ++i) row_fma(a2, W1s + i * 64, dup2(h[i]));
#pragma unroll
        for (int q = 0; q < 32; ++q) {
            float lo, hi; unpack2(a2[q], lo, hi);
            h[2 * q + 0] = __sinf(lo);
            h[2 * q + 1] = __sinf(hi);
        }
    }
    // ---------------- Layer 2 ----------------
    {
        u64 a2[32];
#pragma unroll
        for (int q = 0; q < 32; ++q) a2[q] = 0ull;
        const float *W2s = sW + SW2_OFF;
#pragma unroll
        for (int i = 0; i < 64; ++i) row_fma(a2, W2s + i * 64, dup2(h[i]));
#pragma unroll
        for (int q = 0; q < 32; ++q) {
            float lo, hi; unpack2(a2[q], lo, hi);
            h[2 * q + 0] = __sinf(lo);
            h[2 * q + 1] = __sinf(hi);
        }
    }
    // ---------------- Layer 3 (64 -> 4) ----------------
    u64 a3lo = 0ull, a3hi = 0ull;
    {
        const float *W3s = sW + SW3_OFF;
#pragma unroll
        for (int i = 0; i < 64; ++i) {
            const ulonglong2 w = *(const ulonglong2 *)(W3s + i * 4);
            const u64 xx = dup2(h[i]);
            fma2(a3lo, w.x, xx);
            fma2(a3hi, w.y, xx);
        }
    }
    float o0, o1, o2, o3;
    unpack2(a3lo, o0, o1);
    unpack2(a3hi, o2, o3);

    // Outputs: rgb flattened (N*3) then density (N) — tuple concat order
    out[idx * 3 + 0] = 1.f / (1.f + __expf(-o0));
    out[idx * 3 + 1] = 1.f / (1.f + __expf(-o1));
    out[idx * 3 + 2] = 1.f / (1.f + __expf(-o2));
    out[3 * N + idx] = sel ? __expf(o3 - 1.f) : 0.f;
}

extern "C" void kernel_launch(void *const *d_in, const int *in_sizes, int n_in,
                              void *d_out, int out_size)
{
    const float *positions = (const float *)d_in[0];
    const float *aabb      = (const float *)d_in[1];
    const float *tri       = (const float *)d_in[2];
    const float *W0        = (const float *)d_in[3];
    const float *W1        = (const float *)d_in[4];
    const float *W2        = (const float *)d_in[5];
    const float *W3        = (const float *)d_in[6];
    float *out = (float *)d_out;
    const int N = in_sizes[0] / 3;

    static bool attr_set = false;
    if (!attr_set) {
        cudaFuncSetAttribute(tri_mlp_kernel,
                             cudaFuncAttributeMaxDynamicSharedMemorySize,
                             SMEM_BYTES);
        attr_set = true;
    }

    const int blocks = (N + 255) / 256;
    tri_mlp_kernel<<<blocks, 256, SMEM_BYTES>>>(positions, aabb, tri, W0, W1,
                                                W2, W3, out, N);
}

// round 13
// speedup vs baseline: 1.2750x; 1.2750x over previous
#include <cuda_runtime.h>

typedef unsigned long long u64;

// Binary expansion of 1/(2*pi), preceded by 160 zero bits of padding so the
// window index p0 = e + 10 is always >= 0 for fp32 exponents of a = x*pi.
__constant__ unsigned c_PH[14] = {
    0u, 0u, 0u, 0u, 0u,
    0x28BE60DBu, 0x9391054Au, 0x7F09D5F4u, 0x7D4D3770u,
    0x36D8A566u, 0x4F10E410u, 0x7F9458EAu, 0xF7AEF158u, 0x6DC91B8Eu
};

// ---- packed f32x2 helpers (sm_103a FFMA2 path) -----------------------------
__device__ __forceinline__ void fma2(u64 &acc, u64 w, u64 xx) {
    asm("fma.rn.f32x2 %0, %1, %2, %0;" : "+l"(acc) : "l"(w), "l"(xx));
}
__device__ __forceinline__ u64 dup2(float s) {
    u64 r; asm("mov.b64 %0, {%1, %1};" : "=l"(r) : "f"(s)); return r;
}
__device__ __forceinline__ u64 pack2(float lo, float hi) {
    u64 r; asm("mov.b64 %0, {%1, %2};" : "=l"(r) : "f"(lo), "f"(hi)); return r;
}
__device__ __forceinline__ void unpack2(u64 v, float &lo, float &hi) {
    asm("mov.b64 {%0, %1}, %2;" : "=f"(lo), "=f"(hi) : "l"(v));
}

// 64-wide row FMA for TWO points sharing one weight-row load.
__device__ __forceinline__ void row_fma2(u64 *a0, u64 *a1, const float *wrow,
                                         u64 x0, u64 x1) {
    const ulonglong2 *p = reinterpret_cast<const ulonglong2 *>(wrow);
#pragma unroll
    for (int q = 0; q < 16; ++q) {
        ulonglong2 w = p[q];
        fma2(a0[2 * q + 0], w.x, x0);
        fma2(a0[2 * q + 1], w.y, x0);
        fma2(a1[2 * q + 0], w.x, x1);
        fma2(a1[2 * q + 1], w.y, x1);
    }
}

// Shared layout (floats): [0,19456) W0 | [19456,23552) W1 | [23552,27648) W2 | [27648,27904) W3
#define SW1_OFF 19456
#define SW2_OFF 23552
#define SW3_OFF 27648
#define SMEM_FLOATS 27904
#define SMEM_BYTES (SMEM_FLOATS * 4 + 64)

// ---- Payne-Hanek-style window state: one per (point, dim) ------------------
struct PH {
    u64 Ghi, Glo, m64;
    float sgn;
};
__device__ __forceinline__ PH ph_prep(float xn, const unsigned *sPH) {
    PH S;
    const float a = __fmul_rn(xn, 3.14159274101257324f); // a = fl(x * pi_f32)
    unsigned ab = __float_as_uint(a);
    S.sgn = (ab & 0x80000000u) ? -1.f : 1.f;
    ab &= 0x7FFFFFFFu;
    int e = (int)(ab >> 23);
    unsigned m = ab & 0x007FFFFFu;
    if (e) m |= 0x00800000u; else e = 1;  // denormal: a = m * 2^(1-150)
    const int p0 = e + 10;                // window start bit in padded stream
    int wq = p0 >> 5;
    const int rr = p0 & 31;
    wq = min(wq, 8);
    const u64 A = ((u64)sPH[wq] << 32) | sPH[wq + 1];
    const u64 B = ((u64)sPH[wq + 2] << 32) | sPH[wq + 3];
    const u64 C = ((u64)sPH[wq + 4] << 32) | sPH[wq + 5];
    if (rr) {
        S.Ghi = (A << rr) | (B >> (64 - rr));
        S.Glo = (B << rr) | (C >> (64 - rr));
    } else {
        S.Ghi = A; S.Glo = B;
    }
    S.m64 = (u64)m;
    return S;
}
// One step: emit sin/cos(2^k * a), advance window by one bit (k -> k+1).
// r32 = top 32 bits of frac (centered), so angle = 2*pi * r32 / 2^32.
__device__ __forceinline__ void ph_step(PH &S, float &s, float &c) {
    const u64 fr = S.m64 * S.Ghi;               // frac(m*G), Q0.64
    const int r32 = (int)(unsigned)(fr >> 32);  // centered top 32 bits
    const float ang = (float)r32 * 1.4629180792671596e-9f; // * 2pi/2^32
    __sincosf(ang, &s, &c);                     // |ang| <= pi: fast+accurate
    s *= S.sgn;
    S.Ghi = (S.Ghi << 1) | (S.Glo >> 63);
    S.Glo <<= 1;
}

// Triplane bilinear gather -> 16 features (summed over 3 planes).
__device__ __forceinline__ void gather_feats(const float *__restrict__ tri,
                                             float sc0, float sc1, float sc2,
                                             float *f) {
#pragma unroll
    for (int j = 0; j < 16; ++j) f[j] = 0.f;
    const float scv[3] = {sc0, sc1, sc2};
#pragma unroll
    for (int p = 0; p < 3; ++p) {
        const float cx = (p == 2) ? scv[1] : scv[0];
        const float cy = (p == 0) ? scv[1] : scv[2];
        const float gx = (cx + 1.f) * 0.5f * 31.f;
        const float gy = (cy + 1.f) * 0.5f * 31.f;
        const float x0f = fminf(fmaxf(floorf(gx), 0.f), 31.f);
        const float y0f = fminf(fmaxf(floorf(gy), 0.f), 31.f);
        const int x0 = (int)x0f, y0 = (int)y0f;
        const int x1 = min(x0 + 1, 31), y1 = min(y0 + 1, 31);
        const float wx = gx - x0f, wy = gy - y0f;
        const float w00 = (1.f - wx) * (1.f - wy);
        const float w01 = wx * (1.f - wy);
        const float w10 = (1.f - wx) * wy;
        const float w11 = wx * wy;
        const float *bp = tri + p * 16384;
        const float4 *c00 = (const float4 *)(bp + (y0 * 32 + x0) * 16);
        const float4 *c01 = (const float4 *)(bp + (y0 * 32 + x1) * 16);
        const float4 *c10 = (const float4 *)(bp + (y1 * 32 + x0) * 16);
        const float4 *c11 = (const float4 *)(bp + (y1 * 32 + x1) * 16);
#pragma unroll
        for (int j = 0; j < 4; ++j) {
            const float4 v00 = c00[j], v01 = c01[j], v10 = c10[j], v11 = c11[j];
            f[4 * j + 0] += v00.x * w00 + v01.x * w01 + v10.x * w10 + v11.x * w11;
            f[4 * j + 1] += v00.y * w00 + v01.y * w01 + v10.y * w10 + v11.y * w11;
            f[4 * j + 2] += v00.z * w00 + v01.z * w01 + v10.z * w10 + v11.z * w11;
            f[4 * j + 3] += v00.w * w00 + v01.w * w01 + v10.w * w10 + v11.w * w11;
        }
    }
}

// One 64->64 hidden layer + sin activation for TWO points.
// hp[i] = packed (h_point0[i], h_point1[i]). Output written back into hp.
// Split into two 32-output half-passes to bound register pressure:
// peak live = hp(128) + done(32) + b-accs(64) ~= 224 regs.
__device__ __forceinline__ void hidden_layer2(u64 *hp, const float *Ws) {
    u64 done[32];
    // ---- half 0: outputs 0..31 ----
    {
        u64 b0[16], b1[16];
#pragma unroll
        for (int t = 0; t < 16; ++t) { b0[t] = 0ull; b1[t] = 0ull; }
#pragma unroll
        for (int i = 0; i < 64; ++i) {
            float lo, hi; unpack2(hp[i], lo, hi);
            const u64 x0 = dup2(lo), x1 = dup2(hi);
            const ulonglong2 *p = (const ulonglong2 *)(Ws + i * 64);
#pragma unroll
            for (int q = 0; q < 8; ++q) {
                ulonglong2 w = p[q];
                fma2(b0[2 * q + 0], w.x, x0);
                fma2(b0[2 * q + 1], w.y, x0);
                fma2(b1[2 * q + 0], w.x, x1);
                fma2(b1[2 * q + 1], w.y, x1);
            }
        }
#pragma unroll
        for (int t = 0; t < 16; ++t) {
            float a0l, a0h, a1l, a1h;
            unpack2(b0[t], a0l, a0h);
            unpack2(b1[t], a1l, a1h);
            done[2 * t + 0] = pack2(__sinf(a0l), __sinf(a1l));
            done[2 * t + 1] = pack2(__sinf(a0h), __sinf(a1h));
        }
    }
    // ---- half 1: outputs 32..63 ----
    {
        u64 b0[16], b1[16];
#pragma unroll
        for (int t = 0; t < 16; ++t) { b0[t] = 0ull; b1[t] = 0ull; }
#pragma unroll
        for (int i = 0; i < 64; ++i) {
            float lo, hi; unpack2(hp[i], lo, hi);
            const u64 x0 = dup2(lo), x1 = dup2(hi);
            const ulonglong2 *p = (const ulonglong2 *)(Ws + i * 64 + 32);
#pragma unroll
            for (int q = 0; q < 8; ++q) {
                ulonglong2 w = p[q];
                fma2(b0[2 * q + 0], w.x, x0);
                fma2(b0[2 * q + 1], w.y, x0);
                fma2(b1[2 * q + 0], w.x, x1);
                fma2(b1[2 * q + 1], w.y, x1);
            }
        }
        // hp is dead now: write results in place
#pragma unroll
        for (int t = 0; t < 16; ++t) {
            float a0l, a0h, a1l, a1h;
            unpack2(b0[t], a0l, a0h);
            unpack2(b1[t], a1l, a1h);
            hp[32 + 2 * t + 0] = pack2(__sinf(a0l), __sinf(a1l));
            hp[32 + 2 * t + 1] = pack2(__sinf(a0h), __sinf(a1h));
        }
    }
#pragma unroll
    for (int j = 0; j < 32; ++j) hp[j] = done[j];
}

__global__ void __launch_bounds__(256, 1)
tri_mlp_kernel(const float *__restrict__ pos, const float *__restrict__ aabb,
               const float *__restrict__ tri, const float *__restrict__ gW0,
               const float *__restrict__ gW1, const float *__restrict__ gW2,
               const float *__restrict__ gW3, float *__restrict__ out, int N)
{
    extern __shared__ float sW[];
    unsigned *sPH = (unsigned *)(sW + SMEM_FLOATS);
    const int tid = threadIdx.x;

    // Cooperative weight staging into shared
    {
        float4 *d0 = (float4 *)sW;                 const float4 *s0 = (const float4 *)gW0;
        for (int i = tid; i < 4864; i += 256) d0[i] = s0[i];
        float4 *d1 = (float4 *)(sW + SW1_OFF);     const float4 *s1 = (const float4 *)gW1;
        for (int i = tid; i < 1024; i += 256) d1[i] = s1[i];
        float4 *d2 = (float4 *)(sW + SW2_OFF);     const float4 *s2 = (const float4 *)gW2;
        for (int i = tid; i < 1024; i += 256) d2[i] = s2[i];
        float4 *d3 = (float4 *)(sW + SW3_OFF);     const float4 *s3 = (const float4 *)gW3;
        for (int i = tid; i < 64; i += 256) d3[i] = s3[i];
        if (tid < 14) sPH[tid] = c_PH[tid];
    }
    __syncthreads();

    // Two points per thread: p0 and p0+256 within a 512-point block tile.
    const int p0 = blockIdx.x * 512 + tid;
    if (p0 >= N) return;
    const int p1 = p0 + 256;
    const bool v1 = (p1 < N);
    const int i1 = v1 ? p1 : p0;  // clamp loads; stores guarded

    const float mn0 = aabb[0], mn1 = aabb[1], mn2 = aabb[2];
    const float mx0 = aabb[3], mx1 = aabb[4], mx2 = aabb[5];

    const float ax = pos[p0 * 3 + 0], ay = pos[p0 * 3 + 1], az = pos[p0 * 3 + 2];
    const float bx = pos[i1 * 3 + 0], by = pos[i1 * 3 + 1], bz = pos[i1 * 3 + 2];

    // IEEE-exact normalization (no contraction) to match reference bitwise
    const float xa0 = __fdiv_rn(__fsub_rn(ax, mn0), __fsub_rn(mx0, mn0));
    const float xa1 = __fdiv_rn(__fsub_rn(ay, mn1), __fsub_rn(mx1, mn1));
    const float xa2 = __fdiv_rn(__fsub_rn(az, mn2), __fsub_rn(mx2, mn2));
    const float xb0 = __fdiv_rn(__fsub_rn(bx, mn0), __fsub_rn(mx0, mn0));
    const float xb1 = __fdiv_rn(__fsub_rn(by, mn1), __fsub_rn(mx1, mn1));
    const float xb2 = __fdiv_rn(__fsub_rn(bz, mn2), __fsub_rn(mx2, mn2));
    const bool sel0 = (xa0 > 0.f) && (xa0 < 1.f) && (xa1 > 0.f) && (xa1 < 1.f) &&
                      (xa2 > 0.f) && (xa2 < 1.f);
    const bool sel1 = (xb0 > 0.f) && (xb0 < 1.f) && (xb1 > 0.f) && (xb1 < 1.f) &&
                      (xb2 > 0.f) && (xb2 < 1.f);

    // ---------------- Layer 0 accumulation (streamed features) --------------
    u64 acc0[32], acc1[32];
#pragma unroll
    for (int q = 0; q < 32; ++q) { acc0[q] = 0ull; acc1[q] = 0ull; }

    const float xav[3] = {xa0, xa1, xa2};
    const float xbv[3] = {xb0, xb1, xb2};

#pragma unroll
    for (int d = 0; d < 3; ++d) {
        PH S0 = ph_prep(xav[d], sPH);
        PH S1 = ph_prep(xbv[d], sPH);
        const float *wrow = sW + d * 96 * 64;
#pragma unroll 2
        for (int k = 0; k < 48; ++k) {
            float s0, c0, s1, c1;
            ph_step(S0, s0, c0);
            ph_step(S1, s1, c1);
            row_fma2(acc0, acc1, wrow, dup2(s0), dup2(s1)); wrow += 64;
            row_fma2(acc0, acc1, wrow, dup2(c0), dup2(c1)); wrow += 64;
        }
    }

    // Triplane bilinear features (L2-resident table)
    {
        float f0[16], f1[16];
        gather_feats(tri, 2.f * xa0 - 1.f, 2.f * xa1 - 1.f, 2.f * xa2 - 1.f, f0);
        gather_feats(tri, 2.f * xb0 - 1.f, 2.f * xb1 - 1.f, 2.f * xb2 - 1.f, f1);
#pragma unroll
        for (int t = 0; t < 16; ++t)
            row_fma2(acc0, acc1, sW + (288 + t) * 64, dup2(f0[t]), dup2(f1[t]));
    }

    // sin activation; repack as (point0, point1) pairs per hidden unit
    u64 hp[64];
#pragma unroll
    for (int q = 0; q < 32; ++q) {
        float a0l, a0h, a1l, a1h;
        unpack2(acc0[q], a0l, a0h);
        unpack2(acc1[q], a1l, a1h);
        hp[2 * q + 0] = pack2(__sinf(a0l), __sinf(a1l));
        hp[2 * q + 1] = pack2(__sinf(a0h), __sinf(a1h));
    }

    hidden_layer2(hp, sW + SW1_OFF);
    hidden_layer2(hp, sW + SW2_OFF);

    // ---------------- Layer 3 (64 -> 4) for both points ----------------
    u64 oa01 = 0ull, oa23 = 0ull, ob01 = 0ull, ob23 = 0ull;
    {
        const float *W3s = sW + SW3_OFF;
#pragma unroll
        for (int i = 0; i < 64; ++i) {
            float lo, hi; unpack2(hp[i], lo, hi);
            const u64 x0 = dup2(lo), x1 = dup2(hi);
            const ulonglong2 w = *(const ulonglong2 *)(W3s + i * 4);
            fma2(oa01, w.x, x0);
            fma2(oa23, w.y, x0);
            fma2(ob01, w.x, x1);
            fma2(ob23, w.y, x1);
        }
    }

    float o0, o1, o2, o3;
    unpack2(oa01, o0, o1);
    unpack2(oa23, o2, o3);
    out[p0 * 3 + 0] = 1.f / (1.f + __expf(-o0));
    out[p0 * 3 + 1] = 1.f / (1.f + __expf(-o1));
    out[p0 * 3 + 2] = 1.f / (1.f + __expf(-o2));
    out[3 * N + p0] = sel0 ? __expf(o3 - 1.f) : 0.f;

    if (v1) {
        unpack2(ob01, o0, o1);
        unpack2(ob23, o2, o3);
        out[p1 * 3 + 0] = 1.f / (1.f + __expf(-o0));
        out[p1 * 3 + 1] = 1.f / (1.f + __expf(-o1));
        out[p1 * 3 + 2] = 1.f / (1.f + __expf(-o2));
        out[3 * N + p1] = sel1 ? __expf(o3 - 1.f) : 0.f;
    }
}

extern "C" void kernel_launch(void *const *d_in, const int *in_sizes, int n_in,
                              void *d_out, int out_size)
{
    const float *positions = (const float *)d_in[0];
    const float *aabb      = (const float *)d_in[1];
    const float *tri       = (const float *)d_in[2];
    const float *W0        = (const float *)d_in[3];
    const float *W1        = (const float *)d_in[4];
    const float *W2        = (const float *)d_in[5];
    const float *W3        = (const float *)d_in[6];
    float *out = (float *)d_out;
    const int N = in_sizes[0] / 3;

    static bool attr_set = false;
    if (!attr_set) {
        cudaFuncSetAttribute(tri_mlp_kernel,
                             cudaFuncAttributeMaxDynamicSharedMemorySize,
                             SMEM_BYTES);
        attr_set = true;
    }

    const int blocks = (N + 511) / 512;
    tri_mlp_kernel<<<blocks, 256, SMEM_BYTES>>>(positions, aabb, tri, W0, W1,
                                                W2, W3, out, N);
}

// round 15
// speedup vs baseline: 1.2830x; 1.0062x over previous
#include <cuda_runtime.h>

typedef unsigned long long u64;

// Binary expansion of 1/(2*pi), preceded by 160 zero bits of padding so the
// window index p0 = e + 10 is always >= 0 for fp32 exponents of a = x*pi.
__constant__ unsigned c_PH[14] = {
    0u, 0u, 0u, 0u, 0u,
    0x28BE60DBu, 0x9391054Au, 0x7F09D5F4u, 0x7D4D3770u,
    0x36D8A566u, 0x4F10E410u, 0x7F9458EAu, 0xF7AEF158u, 0x6DC91B8Eu
};

// ---- packed f32x2 helpers (sm_103a FFMA2 path) -----------------------------
__device__ __forceinline__ void fma2(u64 &acc, u64 w, u64 xx) {
    asm("fma.rn.f32x2 %0, %1, %2, %0;" : "+l"(acc) : "l"(w), "l"(xx));
}
__device__ __forceinline__ u64 dup2(float s) {
    u64 r; asm("mov.b64 %0, {%1, %1};" : "=l"(r) : "f"(s)); return r;
}
__device__ __forceinline__ u64 pack2(float lo, float hi) {
    u64 r; asm("mov.b64 %0, {%1, %2};" : "=l"(r) : "f"(lo), "f"(hi)); return r;
}
__device__ __forceinline__ void unpack2(u64 v, float &lo, float &hi) {
    asm("mov.b64 {%0, %1}, %2;" : "=f"(lo), "=f"(hi) : "l"(v));
}

// 64-wide row FMA for TWO points sharing one weight-row load.
__device__ __forceinline__ void row_fma2(u64 *a0, u64 *a1, const float *wrow,
                                         u64 x0, u64 x1) {
    const ulonglong2 *p = reinterpret_cast<const ulonglong2 *>(wrow);
#pragma unroll
    for (int q = 0; q < 16; ++q) {
        ulonglong2 w = p[q];
        fma2(a0[2 * q + 0], w.x, x0);
        fma2(a0[2 * q + 1], w.y, x0);
        fma2(a1[2 * q + 0], w.x, x1);
        fma2(a1[2 * q + 1], w.y, x1);
    }
}

// Shared layout (floats): [0,19456) W0 | [19456,23552) W1 | [23552,27648) W2 | [27648,27904) W3
#define SW1_OFF 19456
#define SW2_OFF 23552
#define SW3_OFF 27648
#define SMEM_FLOATS 27904
#define SMEM_BYTES (SMEM_FLOATS * 4 + 64)

// ---- Payne-Hanek-style window state: one per (point, dim) ------------------
struct PH {
    u64 Ghi, Glo, m64;
    unsigned negmask;  // 0 or 0xFFFFFFFF (sign of a); folded into r32 (exact)
};
__device__ __forceinline__ PH ph_prep(float xn, const unsigned *sPH) {
    PH S;
    const float a = __fmul_rn(xn, 3.14159274101257324f); // a = fl(x * pi_f32)
    unsigned ab = __float_as_uint(a);
    S.negmask = (ab & 0x80000000u) ? 0xFFFFFFFFu : 0u;
    ab &= 0x7FFFFFFFu;
    int e = (int)(ab >> 23);
    unsigned m = ab & 0x007FFFFFu;
    if (e) m |= 0x00800000u; else e = 1;  // denormal: a = m * 2^(1-150)
    const int p0 = e + 10;                // window start bit in padded stream
    int wq = p0 >> 5;
    const int rr = p0 & 31;
    wq = min(wq, 8);
    const u64 A = ((u64)sPH[wq] << 32) | sPH[wq + 1];
    const u64 B = ((u64)sPH[wq + 2] << 32) | sPH[wq + 3];
    const u64 C = ((u64)sPH[wq + 4] << 32) | sPH[wq + 5];
    if (rr) {
        S.Ghi = (A << rr) | (B >> (64 - rr));
        S.Glo = (B << rr) | (C >> (64 - rr));
    } else {
        S.Ghi = A; S.Glo = B;
    }
    S.m64 = (u64)m;
    return S;
}
// Advance prepared window to start at frequency index k0 (0 < k0 < 64).
__device__ __forceinline__ void ph_shift(PH &S, int k0) {
    if (k0 > 0) {
        S.Ghi = (S.Ghi << k0) | (S.Glo >> (64 - k0));
        S.Glo <<= k0;
    }
}
// One step: emit sin/cos(2^k * a), advance window by one bit (k -> k+1).
// r32 = top 32 bits of frac (centered), angle = 2*pi * r32 / 2^32.
// Sign of a folded by exact integer negation (sin odd, cos even).
__device__ __forceinline__ void ph_step(PH &S, float &s, float &c) {
    const u64 fr = S.m64 * S.Ghi;               // frac(m*G), Q0.64
    int r32 = (int)(unsigned)(fr >> 32);        // centered top 32 bits
    r32 = (int)(((unsigned)r32 ^ S.negmask) - S.negmask);
    const float ang = (float)r32 * 1.4629180792671596e-9f; // * 2pi/2^32
    __sincosf(ang, &s, &c);                     // |ang| <= pi: fast+accurate
    S.Ghi = (S.Ghi << 1) | (S.Glo >> 63);
    S.Glo <<= 1;
}

// Frequency block for dim d, k in [kstart, kend), for two points.
// sincos is software-pipelined one iteration ahead so the PH->RRO->MUFU
// dependency chain overlaps the 128 FFMA2s of the previous k.
__device__ __forceinline__ void freq_block(u64 *acc0, u64 *acc1,
                                           const float *sW, const unsigned *sPH,
                                           float xn0, float xn1, int d,
                                           int kstart, int kend) {
    if (kstart >= kend) return;
    PH S0 = ph_prep(xn0, sPH);
    PH S1 = ph_prep(xn1, sPH);
    ph_shift(S0, kstart);
    ph_shift(S1, kstart);
    const float *wrow = sW + (d * 96 + 2 * kstart) * 64;
    float s0, c0, s1, c1;
    ph_step(S0, s0, c0);
    ph_step(S1, s1, c1);
#pragma unroll 2
    for (int k = kstart; k < kend; ++k) {
        const u64 xs0 = dup2(s0), xs1 = dup2(s1);
        const u64 xc0 = dup2(c0), xc1 = dup2(c1);
        if (k + 1 < kend) {      // prefetch next k's sincos
            ph_step(S0, s0, c0);
            ph_step(S1, s1, c1);
        }
        row_fma2(acc0, acc1, wrow, xs0, xs1); wrow += 64;
        row_fma2(acc0, acc1, wrow, xc0, xc1); wrow += 64;
    }
}

// Triplane bilinear gather -> 16 features (summed over 3 planes).
__device__ __forceinline__ void gather_feats(const float *__restrict__ tri,
                                             float sc0, float sc1, float sc2,
                                             float *f) {
#pragma unroll
    for (int j = 0; j < 16; ++j) f[j] = 0.f;
    const float scv[3] = {sc0, sc1, sc2};
#pragma unroll
    for (int p = 0; p < 3; ++p) {
        const float cx = (p == 2) ? scv[1] : scv[0];
        const float cy = (p == 0) ? scv[1] : scv[2];
        const float gx = (cx + 1.f) * 0.5f * 31.f;
        const float gy = (cy + 1.f) * 0.5f * 31.f;
        const float x0f = fminf(fmaxf(floorf(gx), 0.f), 31.f);
        const float y0f = fminf(fmaxf(floorf(gy), 0.f), 31.f);
        const int x0 = (int)x0f, y0 = (int)y0f;
        const int x1 = min(x0 + 1, 31), y1 = min(y0 + 1, 31);
        const float wx = gx - x0f, wy = gy - y0f;
        const float w00 = (1.f - wx) * (1.f - wy);
        const float w01 = wx * (1.f - wy);
        const float w10 = (1.f - wx) * wy;
        const float w11 = wx * wy;
        const float *bp = tri + p * 16384;
        const float4 *c00 = (const float4 *)(bp + (y0 * 32 + x0) * 16);
        const float4 *c01 = (const float4 *)(bp + (y0 * 32 + x1) * 16);
        const float4 *c10 = (const float4 *)(bp + (y1 * 32 + x0) * 16);
        const float4 *c11 = (const float4 *)(bp + (y1 * 32 + x1) * 16);
#pragma unroll
        for (int j = 0; j < 4; ++j) {
            const float4 v00 = c00[j], v01 = c01[j], v10 = c10[j], v11 = c11[j];
            f[4 * j + 0] += v00.x * w00 + v01.x * w01 + v10.x * w10 + v11.x * w11;
            f[4 * j + 1] += v00.y * w00 + v01.y * w01 + v10.y * w10 + v11.y * w11;
            f[4 * j + 2] += v00.z * w00 + v01.z * w01 + v10.z * w10 + v11.z * w11;
            f[4 * j + 3] += v00.w * w00 + v01.w * w01 + v10.w * w10 + v11.w * w11;
        }
    }
}

// One 64->64 hidden layer + sin activation for TWO points.
// hp[i] = packed (h_point0[i], h_point1[i]). Output written back into hp.
// Two 32-output half-passes bound register pressure (~224 peak).
__device__ __forceinline__ void hidden_layer2(u64 *hp, const float *Ws) {
    u64 done[32];
    // ---- half 0: outputs 0..31 ----
    {
        u64 b0[16], b1[16];
#pragma unroll
        for (int t = 0; t < 16; ++t) { b0[t] = 0ull; b1[t] = 0ull; }
#pragma unroll
        for (int i = 0; i < 64; ++i) {
            float lo, hi; unpack2(hp[i], lo, hi);
            const u64 x0 = dup2(lo), x1 = dup2(hi);
            const ulonglong2 *p = (const ulonglong2 *)(Ws + i * 64);
#pragma unroll
            for (int q = 0; q < 8; ++q) {
                ulonglong2 w = p[q];
                fma2(b0[2 * q + 0], w.x, x0);
                fma2(b0[2 * q + 1], w.y, x0);
                fma2(b1[2 * q + 0], w.x, x1);
                fma2(b1[2 * q + 1], w.y, x1);
            }
        }
#pragma unroll
        for (int t = 0; t < 16; ++t) {
            float a0l, a0h, a1l, a1h;
            unpack2(b0[t], a0l, a0h);
            unpack2(b1[t], a1l, a1h);
            done[2 * t + 0] = pack2(__sinf(a0l), __sinf(a1l));
            done[2 * t + 1] = pack2(__sinf(a0h), __sinf(a1h));
        }
    }
    // ---- half 1: outputs 32..63 ----
    {
        u64 b0[16], b1[16];
#pragma unroll
        for (int t = 0; t < 16; ++t) { b0[t] = 0ull; b1[t] = 0ull; }
#pragma unroll
        for (int i = 0; i < 64; ++i) {
            float lo, hi; unpack2(hp[i], lo, hi);
            const u64 x0 = dup2(lo), x1 = dup2(hi);
            const ulonglong2 *p = (const ulonglong2 *)(Ws + i * 64 + 32);
#pragma unroll
            for (int q = 0; q < 8; ++q) {
                ulonglong2 w = p[q];
                fma2(b0[2 * q + 0], w.x, x0);
                fma2(b0[2 * q + 1], w.y, x0);
                fma2(b1[2 * q + 0], w.x, x1);
                fma2(b1[2 * q + 1], w.y, x1);
            }
        }
        // hp is dead now: write results in place
#pragma unroll
        for (int t = 0; t < 16; ++t) {
            float a0l, a0h, a1l, a1h;
            unpack2(b0[t], a0l, a0h);
            unpack2(b1[t], a1l, a1h);
            hp[32 + 2 * t + 0] = pack2(__sinf(a0l), __sinf(a1l));
            hp[32 + 2 * t + 1] = pack2(__sinf(a0h), __sinf(a1h));
        }
    }
#pragma unroll
    for (int j = 0; j < 32; ++j) hp[j] = done[j];
}

__global__ void __launch_bounds__(256, 1)
tri_mlp_kernel(const float *__restrict__ pos, const float *__restrict__ aabb,
               const float *__restrict__ tri, const float *__restrict__ gW0,
               const float *__restrict__ gW1, const float *__restrict__ gW2,
               const float *__restrict__ gW3, float *__restrict__ out, int N)
{
    extern __shared__ float sW[];
    unsigned *sPH = (unsigned *)(sW + SMEM_FLOATS);
    const int tid = threadIdx.x;

    // Cooperative weight staging into shared
    {
        float4 *d0 = (float4 *)sW;                 const float4 *s0 = (const float4 *)gW0;
        for (int i = tid; i < 4864; i += 256) d0[i] = s0[i];
        float4 *d1 = (float4 *)(sW + SW1_OFF);     const float4 *s1 = (const float4 *)gW1;
        for (int i = tid; i < 1024; i += 256) d1[i] = s1[i];
        float4 *d2 = (float4 *)(sW + SW2_OFF);     const float4 *s2 = (const float4 *)gW2;
        for (int i = tid; i < 1024; i += 256) d2[i] = s2[i];
        float4 *d3 = (float4 *)(sW + SW3_OFF);     const float4 *s3 = (const float4 *)gW3;
        for (int i = tid; i < 64; i += 256) d3[i] = s3[i];
        if (tid < 14) sPH[tid] = c_PH[tid];
    }
    __syncthreads();

    // Two points per thread: p0 and p0+256 within a 512-point block tile.
    const int p0 = blockIdx.x * 512 + tid;
    if (p0 >= N) return;
    const int p1 = p0 + 256;
    const bool v1 = (p1 < N);
    const int i1 = v1 ? p1 : p0;  // clamp loads; stores guarded

    // Phase stagger: warps 4-7 are the SECOND warp on each SMSP (SMSP=wid%4).
    // Offset their freq-loop start (dim rotation + k-offset 5) so the two
    // resident warps per SMSP are never in the sincos burst simultaneously.
    const int phase = (tid >> 7) & 1;

    const float mn0 = aabb[0], mn1 = aabb[1], mn2 = aabb[2];
    const float mx0 = aabb[3], mx1 = aabb[4], mx2 = aabb[5];

    const float ax = pos[p0 * 3 + 0], ay = pos[p0 * 3 + 1], az = pos[p0 * 3 + 2];
    const float bx = pos[i1 * 3 + 0], by = pos[i1 * 3 + 1], bz = pos[i1 * 3 + 2];

    // IEEE-exact normalization (no contraction) to match reference bitwise
    const float xa0 = __fdiv_rn(__fsub_rn(ax, mn0), __fsub_rn(mx0, mn0));
    const float xa1 = __fdiv_rn(__fsub_rn(ay, mn1), __fsub_rn(mx1, mn1));
    const float xa2 = __fdiv_rn(__fsub_rn(az, mn2), __fsub_rn(mx2, mn2));
    const float xb0 = __fdiv_rn(__fsub_rn(bx, mn0), __fsub_rn(mx0, mn0));
    const float xb1 = __fdiv_rn(__fsub_rn(by, mn1), __fsub_rn(mx1, mn1));
    const float xb2 = __fdiv_rn(__fsub_rn(bz, mn2), __fsub_rn(mx2, mn2));
    const bool sel0 = (xa0 > 0.f) && (xa0 < 1.f) && (xa1 > 0.f) && (xa1 < 1.f) &&
                      (xa2 > 0.f) && (xa2 < 1.f);
    const bool sel1 = (xb0 > 0.f) && (xb0 < 1.f) && (xb1 > 0.f) && (xb1 < 1.f) &&
                      (xb2 > 0.f) && (xb2 < 1.f);

    // ---------------- Layer 0 accumulation (streamed features) --------------
    u64 acc0[32], acc1[32];
#pragma unroll
    for (int q = 0; q < 32; ++q) { acc0[q] = 0ull; acc1[q] = 0ull; }

    const float xav[3] = {xa0, xa1, xa2};
    const float xbv[3] = {xb0, xb1, xb2};

#pragma unroll
    for (int dd = 0; dd < 3; ++dd) {
        const int d = phase ? ((dd == 2) ? 0 : dd + 1) : dd;  // dim rotation
        const int k0 = phase ? 5 : 0;                          // sub-period offset
        freq_block(acc0, acc1, sW, sPH, xav[d], xbv[d], d, k0, 48);
        if (phase)
            freq_block(acc0, acc1, sW, sPH, xav[d], xbv[d], d, 0, k0);
    }

    // Triplane bilinear features (L2-resident table)
    {
        float f0[16], f1[16];
        gather_feats(tri, 2.f * xa0 - 1.f, 2.f * xa1 - 1.f, 2.f * xa2 - 1.f, f0);
        gather_feats(tri, 2.f * xb0 - 1.f, 2.f * xb1 - 1.f, 2.f * xb2 - 1.f, f1);
#pragma unroll
        for (int t = 0; t < 16; ++t)
            row_fma2(acc0, acc1, sW + (288 + t) * 64, dup2(f0[t]), dup2(f1[t]));
    }

    // sin activation; repack as (point0, point1) pairs per hidden unit
    u64 hp[64];
#pragma unroll
    for (int q = 0; q < 32; ++q) {
        float a0l, a0h, a1l, a1h;
        unpack2(acc0[q], a0l, a0h);
        unpack2(acc1[q], a1l, a1h);
        hp[2 * q + 0] = pack2(__sinf(a0l), __sinf(a1l));
        hp[2 * q + 1] = pack2(__sinf(a0h), __sinf(a1h));
    }

    hidden_layer2(hp, sW + SW1_OFF);
    hidden_layer2(hp, sW + SW2_OFF);

    // ---------------- Layer 3 (64 -> 4) for both points ----------------
    u64 oa01 = 0ull, oa23 = 0ull, ob01 = 0ull, ob23 = 0ull;
    {
        const float *W3s = sW + SW3_OFF;
#pragma unroll
        for (int i = 0; i < 64; ++i) {
            float lo, hi; unpack2(hp[i], lo, hi);
            const u64 x0 = dup2(lo), x1 = dup2(hi);
            const ulonglong2 w = *(const ulonglong2 *)(W3s + i * 4);
            fma2(oa01, w.x, x0);
            fma2(oa23, w.y, x0);
            fma2(ob01, w.x, x1);
            fma2(ob23, w.y, x1);
        }
    }

    float o0, o1, o2, o3;
    unpack2(oa01, o0, o1);
    unpack2(oa23, o2, o3);
    out[p0 * 3 + 0] = 1.f / (1.f + __expf(-o0));
    out[p0 * 3 + 1] = 1.f / (1.f + __expf(-o1));
    out[p0 * 3 + 2] = 1.f / (1.f + __expf(-o2));
    out[3 * N + p0] = sel0 ? __expf(o3 - 1.f) : 0.f;

    if (v1) {
        unpack2(ob01, o0, o1);
        unpack2(ob23, o2, o3);
        out[p1 * 3 + 0] = 1.f / (1.f + __expf(-o0));
        out[p1 * 3 + 1] = 1.f / (1.f + __expf(-o1));
        out[p1 * 3 + 2] = 1.f / (1.f + __expf(-o2));
        out[3 * N + p1] = sel1 ? __expf(o3 - 1.f) : 0.f;
    }
}

extern "C" void kernel_launch(void *const *d_in, const int *in_sizes, int n_in,
                              void *d_out, int out_size)
{
    const float *positions = (const float *)d_in[0];
    const float *aabb      = (const float *)d_in[1];
    const float *tri       = (const float *)d_in[2];
    const float *W0        = (const float *)d_in[3];
    const float *W1        = (const float *)d_in[4];
    const float *W2        = (const float *)d_in[5];
    const float *W3        = (const float *)d_in[6];
    float *out = (float *)d_out;
    const int N = in_sizes[0] / 3;

    static bool attr_set = false;
    if (!attr_set) {
        cudaFuncSetAttribute(tri_mlp_kernel,
                             cudaFuncAttributeMaxDynamicSharedMemorySize,
                             SMEM_BYTES);
        attr_set = true;
    }

    const int blocks = (N + 511) / 512;
    tri_mlp_kernel<<<blocks, 256, SMEM_BYTES>>>(positions, aabb, tri, W0, W1,
                                                W2, W3, out, N);
}